// round 13
// baseline (speedup 1.0000x reference)
#include <cuda_runtime.h>
#include <cuda_bf16.h>
#include <cuda_fp16.h>
#include <math.h>
#include <cstdint>

#define N_NODES 100000
#define N_EDGES 1600000
#define N_PAD 100096            // 782 * 128
#define F_IN 256
#define HID 256
#define NC 40

// ---------------- scratch (static device globals; no allocation) ----------------
__device__ float g_dis[N_NODES];
__device__ int   g_cnt[N_NODES];
__device__ int   g_off[N_NODES];
__device__ int   g_cur[N_NODES];
__device__ int   g_total;
__device__ int   g_ssrc[N_EDGES];
__device__ float g_snorm[N_EDGES];
__device__ __half g_h1h[(size_t)N_NODES * HID];   // fp16 h1 (only copy)
__device__ float  g_h2[(size_t)N_NODES * NC];     // fp32 h2 (self terms)
__device__ __half g_h2h[(size_t)N_NODES * NC];    // fp16 h2 (edge gathers)
__device__ __nv_bfloat16 g_w1t_hi[256 * 256];     // W1^T [n][k]
__device__ __nv_bfloat16 g_w1t_lo[256 * 256];

__device__ __forceinline__ uint32_t smem_u32(const void* p) {
    uint32_t a;
    asm("{ .reg .u64 t; cvta.to.shared.u64 t, %1; cvt.u32.u64 %0, t; }" : "=r"(a) : "l"(p));
    return a;
}
#define CPA16(dst, src) asm volatile("cp.async.cg.shared.global [%0], [%1], 16;" :: "r"(dst), "l"(src))
#define CPC()  asm volatile("cp.async.commit_group;" ::: "memory")
#define CPW(n) asm volatile("cp.async.wait_group %0;" :: "n"(n) : "memory")

// ---------------- preprocessing ----------------
__global__ void k_init() {
    int i = blockIdx.x * blockDim.x + threadIdx.x;
    if (i < N_NODES) { g_dis[i] = 1.0f; g_cnt[i] = 0; g_cur[i] = 0; }
    if (i == 0) g_total = 0;
}

__global__ void k_cnt(const int* __restrict__ dst, const float* __restrict__ ew) {
    int e = blockIdx.x * blockDim.x + threadIdx.x;
    if (e < N_EDGES) {
        int d = dst[e];
        atomicAdd(&g_dis[d], ew[e]);
        atomicAdd(&g_cnt[d], 1);
    }
}

__global__ void k_fin() {
    int i = blockIdx.x * blockDim.x + threadIdx.x;
    if (i < N_NODES) {
        g_dis[i] = rsqrtf(g_dis[i]);
        g_off[i] = atomicAdd(&g_total, g_cnt[i]);
    }
}

__global__ void k_fill(const int* __restrict__ src, const int* __restrict__ dst,
                       const float* __restrict__ ew) {
    int e = blockIdx.x * blockDim.x + threadIdx.x;
    if (e >= N_EDGES) return;
    int d = dst[e];
    int s = src[e];
    int pos = g_off[d] + atomicAdd(&g_cur[d], 1);
    g_ssrc[pos] = s;
    g_snorm[pos] = g_dis[s] * ew[e] * g_dis[d];
}

// ---------------- W1 transpose + bf16 split ----------------
__global__ void k_w1t(const float* __restrict__ W1) {
    int t = blockIdx.x * blockDim.x + threadIdx.x;
    if (t >= 256 * 256) return;
    int n = t >> 8, k = t & 255;
    float w = W1[k * 256 + n];
    __nv_bfloat16 hi = __float2bfloat16(w);
    __nv_bfloat16 lo = __float2bfloat16(w - __bfloat162float(hi));
    g_w1t_hi[t] = hi;
    g_w1t_lo[t] = lo;
}

// ---------------- mma.sync m16n8k16 bf16 ----------------
__device__ __forceinline__ void mma16816(float* c, const uint32_t* a, const uint32_t* b) {
    asm volatile(
        "mma.sync.aligned.m16n8k16.row.col.f32.bf16.bf16.f32 "
        "{%0,%1,%2,%3}, {%4,%5,%6,%7}, {%8,%9}, {%0,%1,%2,%3};\n"
        : "+f"(c[0]), "+f"(c[1]), "+f"(c[2]), "+f"(c[3])
        : "r"(a[0]), "r"(a[1]), "r"(a[2]), "r"(a[3]), "r"(b[0]), "r"(b[1]));
}

// ---------------- GEMM1: 128x256 CTA, 512 threads ----------------
#define SA 72
#define SM_AH 0
#define SM_AL (128 * SA * 2)
#define SM_B0 (2 * 128 * SA * 2)
#define BHALF (256 * SA * 2)
#define BSTAGE (2 * BHALF)
#define SM_G1 (SM_B0 + 2 * BSTAGE)          // 184320

__global__ __launch_bounds__(512) void k_gemm1_mma(const float* __restrict__ x,
                                                   const float* __restrict__ bias) {
    extern __shared__ char smem[];
    const uint32_t sbase = smem_u32(smem);
    const int tid = threadIdx.x;
    const int warp = tid >> 5;
    const int lane = tid & 31;
    const int g = lane >> 2;
    const int tg = lane & 3;
    const int wm = (warp >> 3) * 64;
    const int wn = (warp & 7) * 32;
    const int rowBase = blockIdx.x * 128;

    float4 vr[4];
    auto ldgA = [&](int ch) {
        const int k0 = ch * 64;
#pragma unroll
        for (int i = 0; i < 4; i++) {
            int idx = tid + i * 512;
            int r = idx >> 4, c4 = idx & 15;
            int gr = rowBase + r;
            vr[i] = (gr < N_NODES) ? *(const float4*)(x + (size_t)gr * 256 + k0 + c4 * 4)
                                   : make_float4(0.f, 0.f, 0.f, 0.f);
        }
    };
    auto stsA = [&]() {
#pragma unroll
        for (int i = 0; i < 4; i++) {
            int idx = tid + i * 512;
            int r = idx >> 4, c4 = idx & 15;
            float4 v = vr[i];
            __nv_bfloat16 hx = __float2bfloat16(v.x), hy = __float2bfloat16(v.y);
            __nv_bfloat16 hz = __float2bfloat16(v.z), hw = __float2bfloat16(v.w);
            __nv_bfloat16 lx = __float2bfloat16(v.x - __bfloat162float(hx));
            __nv_bfloat16 ly = __float2bfloat16(v.y - __bfloat162float(hy));
            __nv_bfloat16 lz = __float2bfloat16(v.z - __bfloat162float(hz));
            __nv_bfloat16 lw = __float2bfloat16(v.w - __bfloat162float(hw));
            int o = (r * SA + c4 * 4) * 2;
            *(__nv_bfloat162*)(smem + SM_AH + o)     = __halves2bfloat162(hx, hy);
            *(__nv_bfloat162*)(smem + SM_AH + o + 4) = __halves2bfloat162(hz, hw);
            *(__nv_bfloat162*)(smem + SM_AL + o)     = __halves2bfloat162(lx, ly);
            *(__nv_bfloat162*)(smem + SM_AL + o + 4) = __halves2bfloat162(lz, lw);
        }
    };
    auto loadB = [&](int ch, int buf) {
        const int k0 = ch * 64;
        const uint32_t base = sbase + SM_B0 + buf * BSTAGE;
#pragma unroll
        for (int i = 0; i < 4; i++) {
            int idx = tid + i * 512;
            int r = idx >> 3, u = idx & 7;
            uint32_t d = base + (uint32_t)(r * SA + u * 8) * 2;
            CPA16(d, g_w1t_hi + r * 256 + k0 + u * 8);
            CPA16(d + BHALF, g_w1t_lo + r * 256 + k0 + u * 8);
        }
    };

    float acc[4][4][4];
#pragma unroll
    for (int i = 0; i < 4; i++)
#pragma unroll
        for (int j = 0; j < 4; j++)
#pragma unroll
            for (int r = 0; r < 4; r++) acc[i][j][r] = 0.0f;

    ldgA(0);
    loadB(0, 0); CPC();

    for (int ch = 0; ch < 4; ch++) {
        const int buf = ch & 1;
        stsA();
        if (ch < 3) { ldgA(ch + 1); loadB(ch + 1, buf ^ 1); CPC(); CPW(1); }
        else CPW(0);
        __syncthreads();

        const char* Ah = smem + SM_AH;
        const char* Al = smem + SM_AL;
        const char* Bh = smem + SM_B0 + buf * BSTAGE;
        const char* Bl = Bh + BHALF;

#pragma unroll
        for (int ks = 0; ks < 4; ks++) {
            const int kb = ks * 16;
            uint32_t bh[4][2], bl[4][2];
#pragma unroll
            for (int j = 0; j < 4; j++) {
                int n = wn + j * 8 + g;
                int o = (n * SA + kb + tg * 2) * 2;
                bh[j][0] = *(const uint32_t*)(Bh + o);
                bh[j][1] = *(const uint32_t*)(Bh + o + 16);
                bl[j][0] = *(const uint32_t*)(Bl + o);
                bl[j][1] = *(const uint32_t*)(Bl + o + 16);
            }
#pragma unroll
            for (int i = 0; i < 4; i++) {
                int m = wm + i * 16;
                int o0 = ((m + g) * SA + kb + tg * 2) * 2;
                int o1 = ((m + g + 8) * SA + kb + tg * 2) * 2;
                uint32_t ah[4], al[4];
                ah[0] = *(const uint32_t*)(Ah + o0);
                ah[1] = *(const uint32_t*)(Ah + o1);
                ah[2] = *(const uint32_t*)(Ah + o0 + 16);
                ah[3] = *(const uint32_t*)(Ah + o1 + 16);
                al[0] = *(const uint32_t*)(Al + o0);
                al[1] = *(const uint32_t*)(Al + o1);
                al[2] = *(const uint32_t*)(Al + o0 + 16);
                al[3] = *(const uint32_t*)(Al + o1 + 16);
#pragma unroll
                for (int j = 0; j < 4; j++) {
                    mma16816(acc[i][j], ah, bh[j]);
                    mma16816(acc[i][j], ah, bl[j]);
                    mma16816(acc[i][j], al, bh[j]);
                }
            }
        }
        __syncthreads();
    }

    // epilogue: fp16 h1 only
#pragma unroll
    for (int j = 0; j < 4; j++) {
        int col = wn + j * 8 + tg * 2;
        float bx = __ldg(&bias[col]);
        float by = __ldg(&bias[col + 1]);
#pragma unroll
        for (int i = 0; i < 4; i++) {
            int r0 = rowBase + wm + i * 16 + g;
            if (r0 < N_NODES)
                *(__half2*)(g_h1h + (size_t)r0 * 256 + col) =
                    __floats2half2_rn(acc[i][j][0] + bx, acc[i][j][1] + by);
            int r1 = r0 + 8;
            if (r1 < N_NODES)
                *(__half2*)(g_h1h + (size_t)r1 * 256 + col) =
                    __floats2half2_rn(acc[i][j][2] + bx, acc[i][j][3] + by);
        }
    }
}

// ---------------- fused agg1 + gemm2: block = 4 nodes x 2 warps ----------------
__global__ __launch_bounds__(256) void k_agg1_gemm2(const float* __restrict__ W2,
                                                    const float* __restrict__ b2) {
    __shared__ float sW[HID * NC];     // 40 KB, [k][c]
    __shared__ float sb[NC];
    __shared__ float rows[4][HID];     // aggregated relu'd rows

    const int tid = threadIdx.x;
    for (int i = tid; i < HID * NC; i += 256) sW[i] = W2[i];
    if (tid < NC) sb[tid] = b2[tid];

    const int wid = tid >> 5;
    const int nodeLocal = wid >> 1;
    const int node = blockIdx.x * 4 + nodeLocal;
    const int half = wid & 1;
    const int lane = tid & 31;
    const int fo = half * 32 + lane;   // uint2 index (4 feats)

    if (node < N_NODES) {
        const uint2* hh = (const uint2*)g_h1h;
        float dv = g_dis[node];
        float self = dv * dv;
        uint2 us = __ldg(&hh[(size_t)node * 64 + fo]);
        float2 sa = __half22float2(*(__half2*)&us.x);
        float2 sbv = __half22float2(*(__half2*)&us.y);
        float4 acc = make_float4(sa.x * self, sa.y * self, sbv.x * self, sbv.y * self);

        int p = g_off[node], end = p + g_cnt[node];
        for (; p + 2 <= end; p += 2) {
            int s0 = __ldg(&g_ssrc[p]);
            int s1 = __ldg(&g_ssrc[p + 1]);
            float n0 = __ldg(&g_snorm[p]);
            float n1 = __ldg(&g_snorm[p + 1]);
            uint2 u0 = __ldg(&hh[(size_t)s0 * 64 + fo]);
            uint2 u1 = __ldg(&hh[(size_t)s1 * 64 + fo]);
            float2 a0 = __half22float2(*(__half2*)&u0.x);
            float2 b0 = __half22float2(*(__half2*)&u0.y);
            float2 a1 = __half22float2(*(__half2*)&u1.x);
            float2 b1 = __half22float2(*(__half2*)&u1.y);
            acc.x = fmaf(a0.x, n0, acc.x); acc.y = fmaf(a0.y, n0, acc.y);
            acc.z = fmaf(b0.x, n0, acc.z); acc.w = fmaf(b0.y, n0, acc.w);
            acc.x = fmaf(a1.x, n1, acc.x); acc.y = fmaf(a1.y, n1, acc.y);
            acc.z = fmaf(b1.x, n1, acc.z); acc.w = fmaf(b1.y, n1, acc.w);
        }
        if (p < end) {
            int s = __ldg(&g_ssrc[p]);
            float nm = __ldg(&g_snorm[p]);
            uint2 u = __ldg(&hh[(size_t)s * 64 + fo]);
            float2 a = __half22float2(*(__half2*)&u.x);
            float2 b = __half22float2(*(__half2*)&u.y);
            acc.x = fmaf(a.x, nm, acc.x); acc.y = fmaf(a.y, nm, acc.y);
            acc.z = fmaf(b.x, nm, acc.z); acc.w = fmaf(b.y, nm, acc.w);
        }

        acc.x = fmaxf(acc.x, 0.f); acc.y = fmaxf(acc.y, 0.f);
        acc.z = fmaxf(acc.z, 0.f); acc.w = fmaxf(acc.w, 0.f);
        *(float4*)&rows[nodeLocal][fo * 4] = acc;
    }
    __syncthreads();

    // gemm2 phase: 160 threads, one (node, class) each
    if (tid < 160) {
        int nl = tid / NC;
        int c = tid - nl * NC;
        int n2 = blockIdx.x * 4 + nl;
        if (n2 < N_NODES) {
            float acc = sb[c];
            const float* r = rows[nl];
#pragma unroll 8
            for (int k = 0; k < HID; k++)
                acc = fmaf(r[k], sW[k * NC + c], acc);
            g_h2[(size_t)n2 * NC + c] = acc;
            g_h2h[(size_t)n2 * NC + c] = __float2half_rn(acc);
        }
    }
}

// ---------------- agg2 + log_softmax fused (fp16 edge gathers) ----------------
__global__ __launch_bounds__(256) void k_agg2_lsm(float* __restrict__ out) {
    int node = blockIdx.x * 8 + (threadIdx.x >> 5);
    if (node >= N_NODES) return;
    int lane = threadIdx.x & 31;

    float dv = g_dis[node];
    float self = dv * dv;
    const float* hd = g_h2 + (size_t)node * NC;
    float a0 = hd[lane] * self;
    float a1 = (lane < 8) ? hd[lane + 32] * self : 0.f;

    int beg = g_off[node], end = beg + g_cnt[node];
    for (int p = beg; p < end; p++) {
        int s = __ldg(&g_ssrc[p]);
        float nm = __ldg(&g_snorm[p]);
        const __half* hs = g_h2h + (size_t)s * NC;
        a0 = fmaf(__half2float(__ldg(&hs[lane])), nm, a0);
        if (lane < 8) a1 = fmaf(__half2float(__ldg(&hs[lane + 32])), nm, a1);
    }

    float m = (lane < 8) ? fmaxf(a0, a1) : a0;
#pragma unroll
    for (int o = 16; o >= 1; o >>= 1)
        m = fmaxf(m, __shfl_xor_sync(0xFFFFFFFFu, m, o));
    float s = __expf(a0 - m) + ((lane < 8) ? __expf(a1 - m) : 0.f);
#pragma unroll
    for (int o = 16; o >= 1; o >>= 1)
        s += __shfl_xor_sync(0xFFFFFFFFu, s, o);
    float ls = m + logf(s);

    float* op = out + (size_t)node * NC;
    op[lane] = a0 - ls;
    if (lane < 8) op[lane + 32] = a1 - ls;
}

// ---------------- launch (forked: preprocessing || gemm1 path) ----------------
extern "C" void kernel_launch(void* const* d_in, const int* in_sizes, int n_in,
                              void* d_out, int out_size) {
    const float* x  = (const float*)d_in[0];
    const int*   ei = (const int*)d_in[1];
    const float* ew = (const float*)d_in[2];
    const float* W1 = (const float*)d_in[3];
    const float* b1 = (const float*)d_in[4];
    const float* W2 = (const float*)d_in[5];
    const float* b2 = (const float*)d_in[6];
    float* out = (float*)d_out;

    const int* src = ei;
    const int* dst = ei + N_EDGES;

    cudaFuncSetAttribute(k_gemm1_mma, cudaFuncAttributeMaxDynamicSharedMemorySize, SM_G1);

    cudaStream_t s2;
    cudaStreamCreateWithFlags(&s2, cudaStreamNonBlocking);
    cudaEvent_t eF, eJ;
    cudaEventCreateWithFlags(&eF, cudaEventDisableTiming);
    cudaEventCreateWithFlags(&eJ, cudaEventDisableTiming);

    // fork: gemm1 path on s2 (independent of edge preprocessing)
    cudaEventRecord(eF, 0);
    cudaStreamWaitEvent(s2, eF, 0);
    k_w1t<<<256, 256, 0, s2>>>(W1);
    k_gemm1_mma<<<N_PAD / 128, 512, SM_G1, s2>>>(x, b1);
    cudaEventRecord(eJ, s2);

    // preprocessing on main stream
    k_init<<<(N_NODES + 255) / 256, 256>>>();
    k_cnt<<<(N_EDGES + 255) / 256, 256>>>(dst, ew);
    k_fin<<<(N_NODES + 255) / 256, 256>>>();
    k_fill<<<(N_EDGES + 255) / 256, 256>>>(src, dst, ew);

    // join, then dependent chain
    cudaStreamWaitEvent(0, eJ, 0);
    k_agg1_gemm2<<<(N_NODES + 3) / 4, 256>>>(W2, b2);
    k_agg2_lsm<<<(N_NODES + 7) / 8, 256>>>(out);
}

// round 16
// speedup vs baseline: 1.2751x; 1.2751x over previous
// GCN r16 — R14 resubmission (behavioPrally identical; content-hash bump only)
#include <cuda_runtime.h>
#include <cuda_bf16.h>
#include <cuda_fp16.h>
#include <math.h>
#include <cstdint>

#define N_NODES 100000
#define N_EDGES 1600000
#define N_PAD 100096            // 782 * 128
#define F_IN 256
#define HID 256
#define NC 40

// ---------------- scratch (static device globals; no allocation) ----------------
__device__ float g_dis[N_NODES];
__device__ int   g_cnt[N_NODES];
__device__ int   g_off[N_NODES];
__device__ int   g_cur[N_NODES];
__device__ int   g_total;
__device__ int   g_ssrc[N_EDGES];
__device__ float g_snorm[N_EDGES];
__device__ __half g_h1h[(size_t)N_NODES * HID];   // fp16 h1 (only copy)
__device__ __half g_a1h[(size_t)N_NODES * HID];   // fp16 relu(agg1)
__device__ float  g_h2[(size_t)N_NODES * NC];     // fp32 h2 (self terms)
__device__ __half g_h2h[(size_t)N_NODES * NC];    // fp16 h2 (edge gathers)
__device__ __nv_bfloat16 g_w1t_hi[256 * 256];     // W1^T [n][k]
__device__ __nv_bfloat16 g_w1t_lo[256 * 256];

__device__ __forceinline__ uint32_t smem_u32(const void* p) {
    uint32_t a;
    asm("{ .reg .u64 t; cvta.to.shared.u64 t, %1; cvt.u32.u64 %0, t; }" : "=r"(a) : "l"(p));
    return a;
}
#define CPA16(dst, src) asm volatile("cp.async.cg.shared.global [%0], [%1], 16;" :: "r"(dst), "l"(src))
#define CPC()  asm volatile("cp.async.commit_group;" ::: "memory")
#define CPW(n) asm volatile("cp.async.wait_group %0;" :: "n"(n) : "memory")

// ---------------- preprocessing ----------------
__global__ void k_init() {
    int i = blockIdx.x * blockDim.x + threadIdx.x;
    if (i < N_NODES) { g_dis[i] = 1.0f; g_cnt[i] = 0; g_cur[i] = 0; }
    if (i == 0) g_total = 0;
}

__global__ void k_cnt(const int* __restrict__ dst, const float* __restrict__ ew) {
    int e = blockIdx.x * blockDim.x + threadIdx.x;
    if (e < N_EDGES) {
        int d = dst[e];
        atomicAdd(&g_dis[d], ew[e]);
        atomicAdd(&g_cnt[d], 1);
    }
}

__global__ void k_fin() {
    int i = blockIdx.x * blockDim.x + threadIdx.x;
    if (i < N_NODES) {
        g_dis[i] = rsqrtf(g_dis[i]);
        g_off[i] = atomicAdd(&g_total, g_cnt[i]);
    }
}

__global__ void k_fill(const int* __restrict__ src, const int* __restrict__ dst,
                       const float* __restrict__ ew) {
    int e = blockIdx.x * blockDim.x + threadIdx.x;
    if (e >= N_EDGES) return;
    int d = dst[e];
    int s = src[e];
    int pos = g_off[d] + atomicAdd(&g_cur[d], 1);
    g_ssrc[pos] = s;
    g_snorm[pos] = g_dis[s] * ew[e] * g_dis[d];
}

// ---------------- W1 transpose + bf16 split ----------------
__global__ void k_w1t(const float* __restrict__ W1) {
    int t = blockIdx.x * blockDim.x + threadIdx.x;
    if (t >= 256 * 256) return;
    int n = t >> 8, k = t & 255;
    float w = W1[k * 256 + n];
    __nv_bfloat16 hi = __float2bfloat16(w);
    __nv_bfloat16 lo = __float2bfloat16(w - __bfloat162float(hi));
    g_w1t_hi[t] = hi;
    g_w1t_lo[t] = lo;
}

// ---------------- mma.sync m16n8k16 bf16 ----------------
__device__ __forceinline__ void mma16816(float* c, const uint32_t* a, const uint32_t* b) {
    asm volatile(
        "mma.sync.aligned.m16n8k16.row.col.f32.bf16.bf16.f32 "
        "{%0,%1,%2,%3}, {%4,%5,%6,%7}, {%8,%9}, {%0,%1,%2,%3};\n"
        : "+f"(c[0]), "+f"(c[1]), "+f"(c[2]), "+f"(c[3])
        : "r"(a[0]), "r"(a[1]), "r"(a[2]), "r"(a[3]), "r"(b[0]), "r"(b[1]));
}

// ---------------- GEMM1: 128x256 CTA, 512 threads ----------------
#define SA 72
#define SM_AH 0
#define SM_AL (128 * SA * 2)
#define SM_B0 (2 * 128 * SA * 2)
#define BHALF (256 * SA * 2)
#define BSTAGE (2 * BHALF)
#define SM_G1 (SM_B0 + 2 * BSTAGE)          // 184320

__global__ __launch_bounds__(512) void k_gemm1_mma(const float* __restrict__ x,
                                                   const float* __restrict__ bias) {
    extern __shared__ char smem[];
    const uint32_t sbase = smem_u32(smem);
    const int tid = threadIdx.x;
    const int warp = tid >> 5;
    const int lane = tid & 31;
    const int g = lane >> 2;
    const int tg = lane & 3;
    const int wm = (warp >> 3) * 64;
    const int wn = (warp & 7) * 32;
    const int rowBase = blockIdx.x * 128;

    float4 vr[4];
    auto ldgA = [&](int ch) {
        const int k0 = ch * 64;
#pragma unroll
        for (int i = 0; i < 4; i++) {
            int idx = tid + i * 512;
            int r = idx >> 4, c4 = idx & 15;
            int gr = rowBase + r;
            vr[i] = (gr < N_NODES) ? *(const float4*)(x + (size_t)gr * 256 + k0 + c4 * 4)
                                   : make_float4(0.f, 0.f, 0.f, 0.f);
        }
    };
    auto stsA = [&]() {
#pragma unroll
        for (int i = 0; i < 4; i++) {
            int idx = tid + i * 512;
            int r = idx >> 4, c4 = idx & 15;
            float4 v = vr[i];
            __nv_bfloat16 hx = __float2bfloat16(v.x), hy = __float2bfloat16(v.y);
            __nv_bfloat16 hz = __float2bfloat16(v.z), hw = __float2bfloat16(v.w);
            __nv_bfloat16 lx = __float2bfloat16(v.x - __bfloat162float(hx));
            __nv_bfloat16 ly = __float2bfloat16(v.y - __bfloat162float(hy));
            __nv_bfloat16 lz = __float2bfloat16(v.z - __bfloat162float(hz));
            __nv_bfloat16 lw = __float2bfloat16(v.w - __bfloat162float(hw));
            int o = (r * SA + c4 * 4) * 2;
            *(__nv_bfloat162*)(smem + SM_AH + o)     = __halves2bfloat162(hx, hy);
            *(__nv_bfloat162*)(smem + SM_AH + o + 4) = __halves2bfloat162(hz, hw);
            *(__nv_bfloat162*)(smem + SM_AL + o)     = __halves2bfloat162(lx, ly);
            *(__nv_bfloat162*)(smem + SM_AL + o + 4) = __halves2bfloat162(lz, lw);
        }
    };
    auto loadB = [&](int ch, int buf) {
        const int k0 = ch * 64;
        const uint32_t base = sbase + SM_B0 + buf * BSTAGE;
#pragma unroll
        for (int i = 0; i < 4; i++) {
            int idx = tid + i * 512;
            int r = idx >> 3, u = idx & 7;
            uint32_t d = base + (uint32_t)(r * SA + u * 8) * 2;
            CPA16(d, g_w1t_hi + r * 256 + k0 + u * 8);
            CPA16(d + BHALF, g_w1t_lo + r * 256 + k0 + u * 8);
        }
    };

    float acc[4][4][4];
#pragma unroll
    for (int i = 0; i < 4; i++)
#pragma unroll
        for (int j = 0; j < 4; j++)
#pragma unroll
            for (int r = 0; r < 4; r++) acc[i][j][r] = 0.0f;

    ldgA(0);
    loadB(0, 0); CPC();

    for (int ch = 0; ch < 4; ch++) {
        const int buf = ch & 1;
        stsA();
        if (ch < 3) { ldgA(ch + 1); loadB(ch + 1, buf ^ 1); CPC(); CPW(1); }
        else CPW(0);
        __syncthreads();

        const char* Ah = smem + SM_AH;
        const char* Al = smem + SM_AL;
        const char* Bh = smem + SM_B0 + buf * BSTAGE;
        const char* Bl = Bh + BHALF;

#pragma unroll
        for (int ks = 0; ks < 4; ks++) {
            const int kb = ks * 16;
            uint32_t bh[4][2], bl[4][2];
#pragma unroll
            for (int j = 0; j < 4; j++) {
                int n = wn + j * 8 + g;
                int o = (n * SA + kb + tg * 2) * 2;
                bh[j][0] = *(const uint32_t*)(Bh + o);
                bh[j][1] = *(const uint32_t*)(Bh + o + 16);
                bl[j][0] = *(const uint32_t*)(Bl + o);
                bl[j][1] = *(const uint32_t*)(Bl + o + 16);
            }
#pragma unroll
            for (int i = 0; i < 4; i++) {
                int m = wm + i * 16;
                int o0 = ((m + g) * SA + kb + tg * 2) * 2;
                int o1 = ((m + g + 8) * SA + kb + tg * 2) * 2;
                uint32_t ah[4], al[4];
                ah[0] = *(const uint32_t*)(Ah + o0);
                ah[1] = *(const uint32_t*)(Ah + o1);
                ah[2] = *(const uint32_t*)(Ah + o0 + 16);
                ah[3] = *(const uint32_t*)(Ah + o1 + 16);
                al[0] = *(const uint32_t*)(Al + o0);
                al[1] = *(const uint32_t*)(Al + o1);
                al[2] = *(const uint32_t*)(Al + o0 + 16);
                al[3] = *(const uint32_t*)(Al + o1 + 16);
#pragma unroll
                for (int j = 0; j < 4; j++) {
                    mma16816(acc[i][j], ah, bh[j]);
                    mma16816(acc[i][j], ah, bl[j]);
                    mma16816(acc[i][j], al, bh[j]);
                }
            }
        }
        __syncthreads();
    }

    // epilogue: fp16 h1 only
#pragma unroll
    for (int j = 0; j < 4; j++) {
        int col = wn + j * 8 + tg * 2;
        float bx = __ldg(&bias[col]);
        float by = __ldg(&bias[col + 1]);
#pragma unroll
        for (int i = 0; i < 4; i++) {
            int r0 = rowBase + wm + i * 16 + g;
            if (r0 < N_NODES)
                *(__half2*)(g_h1h + (size_t)r0 * 256 + col) =
                    __floats2half2_rn(acc[i][j][0] + bx, acc[i][j][1] + by);
            int r1 = r0 + 8;
            if (r1 < N_NODES)
                *(__half2*)(g_h1h + (size_t)r1 * 256 + col) =
                    __floats2half2_rn(acc[i][j][2] + bx, acc[i][j][3] + by);
        }
    }
}

// ---------------- agg1: 2 warps per node; fp16 gathers, fp32 accum, fp16 out ----------------
__global__ __launch_bounds__(256) void k_agg1() {
    int wid = blockIdx.x * 8 + (threadIdx.x >> 5);
    int node = wid >> 1;
    if (node >= N_NODES) return;
    int half = wid & 1;
    int lane = threadIdx.x & 31;
    int fo = half * 32 + lane;          // uint2 index (4 feats)

    const uint2* hh = (const uint2*)g_h1h;
    float dv = g_dis[node];
    float self = dv * dv;
    uint2 us = __ldg(&hh[(size_t)node * 64 + fo]);
    float2 sa = __half22float2(*(__half2*)&us.x);
    float2 sb = __half22float2(*(__half2*)&us.y);
    float4 acc = make_float4(sa.x * self, sa.y * self, sb.x * self, sb.y * self);

    int p = g_off[node], end = p + g_cnt[node];
    for (; p + 2 <= end; p += 2) {
        int s0 = __ldg(&g_ssrc[p]);
        int s1 = __ldg(&g_ssrc[p + 1]);
        float n0 = __ldg(&g_snorm[p]);
        float n1 = __ldg(&g_snorm[p + 1]);
        uint2 u0 = __ldg(&hh[(size_t)s0 * 64 + fo]);
        uint2 u1 = __ldg(&hh[(size_t)s1 * 64 + fo]);
        float2 a0 = __half22float2(*(__half2*)&u0.x);
        float2 b0 = __half22float2(*(__half2*)&u0.y);
        float2 a1 = __half22float2(*(__half2*)&u1.x);
        float2 b1 = __half22float2(*(__half2*)&u1.y);
        acc.x = fmaf(a0.x, n0, acc.x); acc.y = fmaf(a0.y, n0, acc.y);
        acc.z = fmaf(b0.x, n0, acc.z); acc.w = fmaf(b0.y, n0, acc.w);
        acc.x = fmaf(a1.x, n1, acc.x); acc.y = fmaf(a1.y, n1, acc.y);
        acc.z = fmaf(b1.x, n1, acc.z); acc.w = fmaf(b1.y, n1, acc.w);
    }
    if (p < end) {
        int s = __ldg(&g_ssrc[p]);
        float nm = __ldg(&g_snorm[p]);
        uint2 u = __ldg(&hh[(size_t)s * 64 + fo]);
        float2 a = __half22float2(*(__half2*)&u.x);
        float2 b = __half22float2(*(__half2*)&u.y);
        acc.x = fmaf(a.x, nm, acc.x); acc.y = fmaf(a.y, nm, acc.y);
        acc.z = fmaf(b.x, nm, acc.z); acc.w = fmaf(b.y, nm, acc.w);
    }

    acc.x = fmaxf(acc.x, 0.f); acc.y = fmaxf(acc.y, 0.f);
    acc.z = fmaxf(acc.z, 0.f); acc.w = fmaxf(acc.w, 0.f);
    uint2 outv;
    *(__half2*)&outv.x = __floats2half2_rn(acc.x, acc.y);
    *(__half2*)&outv.y = __floats2half2_rn(acc.z, acc.w);
    ((uint2*)g_a1h)[(size_t)node * 64 + fo] = outv;
}

// ---------------- GEMM2: g_h2 = a1h @ W2 + b2 (fp16 in, fp32 accum) ----------------
__global__ __launch_bounds__(256) void k_gemm2(const float* __restrict__ W2,
                                               const float* __restrict__ b2) {
    __shared__ float sW[HID * NC];
    for (int i = threadIdx.x; i < HID * NC; i += 256) sW[i] = W2[i];
    __syncthreads();

    int row = blockIdx.x * 64 + (threadIdx.x >> 2);
    int cg = (threadIdx.x & 3) * 10;
    if (row >= N_NODES) return;

    float acc[10];
#pragma unroll
    for (int c = 0; c < 10; c++) acc[c] = b2[cg + c];

    const uint2* a = (const uint2*)(g_a1h + (size_t)row * HID);
    for (int k4 = 0; k4 < HID / 4; k4++) {
        uint2 u = __ldg(&a[k4]);
        float2 p0 = __half22float2(*(__half2*)&u.x);
        float2 p1 = __half22float2(*(__half2*)&u.y);
        float v[4] = {p0.x, p0.y, p1.x, p1.y};
#pragma unroll
        for (int kk = 0; kk < 4; kk++) {
            int k = k4 * 4 + kk;
#pragma unroll
            for (int c = 0; c < 10; c++)
                acc[c] = fmaf(v[kk], sW[k * NC + cg + c], acc[c]);
        }
    }
#pragma unroll
    for (int c = 0; c < 10; c++) {
        g_h2[(size_t)row * NC + cg + c] = acc[c];
        g_h2h[(size_t)row * NC + cg + c] = __float2half_rn(acc[c]);
    }
}

// ---------------- agg2 + log_softmax fused (fp16 edge gathers) ----------------
__global__ __launch_bounds__(256) void k_agg2_lsm(float* __restrict__ out) {
    int node = blockIdx.x * 8 + (threadIdx.x >> 5);
    if (node >= N_NODES) return;
    int lane = threadIdx.x & 31;

    float dv = g_dis[node];
    float self = dv * dv;
    const float* hd = g_h2 + (size_t)node * NC;
    float a0 = hd[lane] * self;
    float a1 = (lane < 8) ? hd[lane + 32] * self : 0.f;

    int beg = g_off[node], end = beg + g_cnt[node];
    for (int p = beg; p < end; p++) {
        int s = __ldg(&g_ssrc[p]);
        float nm = __ldg(&g_snorm[p]);
        const __half* hs = g_h2h + (size_t)s * NC;
        a0 = fmaf(__half2float(__ldg(&hs[lane])), nm, a0);
        if (lane < 8) a1 = fmaf(__half2float(__ldg(&hs[lane + 32])), nm, a1);
    }

    float m = (lane < 8) ? fmaxf(a0, a1) : a0;
#pragma unroll
    for (int o = 16; o >= 1; o >>= 1)
        m = fmaxf(m, __shfl_xor_sync(0xFFFFFFFFu, m, o));
    float s = __expf(a0 - m) + ((lane < 8) ? __expf(a1 - m) : 0.f);
#pragma unroll
    for (int o = 16; o >= 1; o >>= 1)
        s += __shfl_xor_sync(0xFFFFFFFFu, s, o);
    float ls = m + logf(s);

    float* op = out + (size_t)node * NC;
    op[lane] = a0 - ls;
    if (lane < 8) op[lane + 32] = a1 - ls;
}

// ---------------- launch (forked: preprocessing || gemm1 path) ----------------
extern "C" void kernel_launch(void* const* d_in, const int* in_sizes, int n_in,
                              void* d_out, int out_size) {
    const float* x  = (const float*)d_in[0];
    const int*   ei = (const int*)d_in[1];
    const float* ew = (const float*)d_in[2];
    const float* W1 = (const float*)d_in[3];
    const float* b1 = (const float*)d_in[4];
    const float* W2 = (const float*)d_in[5];
    const float* b2 = (const float*)d_in[6];
    float* out = (float*)d_out;

    const int* src = ei;
    const int* dst = ei + N_EDGES;

    cudaFuncSetAttribute(k_gemm1_mma, cudaFuncAttributeMaxDynamicSharedMemorySize, SM_G1);

    cudaStream_t s2;
    cudaStreamCreateWithFlags(&s2, cudaStreamNonBlocking);
    cudaEvent_t eF, eJ;
    cudaEventCreateWithFlags(&eF, cudaEventDisableTiming);
    cudaEventCreateWithFlags(&eJ, cudaEventDisableTiming);

    // fork: gemm1 path on s2 (independent of edge preprocessing)
    cudaEventRecord(eF, 0);
    cudaStreamWaitEvent(s2, eF, 0);
    k_w1t<<<256, 256, 0, s2>>>(W1);
    k_gemm1_mma<<<N_PAD / 128, 512, SM_G1, s2>>>(x, b1);
    cudaEventRecord(eJ, s2);

    // preprocessing on main stream
    k_init<<<(N_NODES + 255) / 256, 256>>>();
    k_cnt<<<(N_EDGES + 255) / 256, 256>>>(dst, ew);
    k_fin<<<(N_NODES + 255) / 256, 256>>>();
    k_fill<<<(N_EDGES + 255) / 256, 256>>>(src, dst, ew);

    // join, then dependent chain
    cudaStreamWaitEvent(0, eJ, 0);
    k_agg1<<<(2 * N_NODES + 7) / 8, 256>>>();
    k_gemm2<<<(N_NODES + 63) / 64, 256>>>(W2, b2);
    k_agg2_lsm<<<(N_NODES + 7) / 8, 256>>>(out);
}

// round 17
// speedup vs baseline: 1.6660x; 1.3066x over previous
// GCN r17 — tensor-core gemm2 (fp16 hi/lo W2) + agg1 unroll4
#include <cuda_runtime.h>
#include <cuda_bf16.h>
#include <cuda_fp16.h>
#include <math.h>
#include <cstdint>

#define N_NODES 100000
#define N_EDGES 1600000
#define N_PAD 100096            // 782 * 128
#define F_IN 256
#define HID 256
#define NC 40

// ---------------- scratch (static device globals; no allocation) ----------------
__device__ float g_dis[N_NODES];
__device__ int   g_cnt[N_NODES];
__device__ int   g_off[N_NODES];
__device__ int   g_cur[N_NODES];
__device__ int   g_total;
__device__ int   g_ssrc[N_EDGES];
__device__ float g_snorm[N_EDGES];
__device__ __half g_h1h[(size_t)N_NODES * HID];   // fp16 h1 (only copy)
__device__ __half g_a1h[(size_t)N_PAD * HID];     // fp16 relu(agg1), padded (pad rows zero-init)
__device__ float  g_h2[(size_t)N_NODES * NC];     // fp32 h2 (self terms)
__device__ __half g_h2h[(size_t)N_NODES * NC];    // fp16 h2 (edge gathers)
__device__ __nv_bfloat16 g_w1t_hi[256 * 256];     // W1^T [n][k]
__device__ __nv_bfloat16 g_w1t_lo[256 * 256];
__device__ __half g_w2t_hi[64 * 256];             // W2^T [n][k] fp16 hi (n padded to 64)
__device__ __half g_w2t_lo[64 * 256];             // fp16 lo correction

__device__ __forceinline__ uint32_t smem_u32(const void* p) {
    uint32_t a;
    asm("{ .reg .u64 t; cvta.to.shared.u64 t, %1; cvt.u32.u64 %0, t; }" : "=r"(a) : "l"(p));
    return a;
}
#define CPA16(dst, src) asm volatile("cp.async.cg.shared.global [%0], [%1], 16;" :: "r"(dst), "l"(src))
#define CPC()  asm volatile("cp.async.commit_group;" ::: "memory")
#define CPW(n) asm volatile("cp.async.wait_group %0;" :: "n"(n) : "memory")

// ---------------- preprocessing ----------------
__global__ void k_init() {
    int i = blockIdx.x * blockDim.x + threadIdx.x;
    if (i < N_NODES) { g_dis[i] = 1.0f; g_cnt[i] = 0; g_cur[i] = 0; }
    if (i == 0) g_total = 0;
}

__global__ void k_cnt(const int* __restrict__ dst, const float* __restrict__ ew) {
    int e = blockIdx.x * blockDim.x + threadIdx.x;
    if (e < N_EDGES) {
        int d = dst[e];
        atomicAdd(&g_dis[d], ew[e]);
        atomicAdd(&g_cnt[d], 1);
    }
}

__global__ void k_fin() {
    int i = blockIdx.x * blockDim.x + threadIdx.x;
    if (i < N_NODES) {
        g_dis[i] = rsqrtf(g_dis[i]);
        g_off[i] = atomicAdd(&g_total, g_cnt[i]);
    }
}

__global__ void k_fill(const int* __restrict__ src, const int* __restrict__ dst,
                       const float* __restrict__ ew) {
    int e = blockIdx.x * blockDim.x + threadIdx.x;
    if (e >= N_EDGES) return;
    int d = dst[e];
    int s = src[e];
    int pos = g_off[d] + atomicAdd(&g_cur[d], 1);
    g_ssrc[pos] = s;
    g_snorm[pos] = g_dis[s] * ew[e] * g_dis[d];
}

// ---------------- W1 transpose + bf16 split ----------------
__global__ void k_w1t(const float* __restrict__ W1) {
    int t = blockIdx.x * blockDim.x + threadIdx.x;
    if (t >= 256 * 256) return;
    int n = t >> 8, k = t & 255;
    float w = W1[k * 256 + n];
    __nv_bfloat16 hi = __float2bfloat16(w);
    __nv_bfloat16 lo = __float2bfloat16(w - __bfloat162float(hi));
    g_w1t_hi[t] = hi;
    g_w1t_lo[t] = lo;
}

// ---------------- W2 transpose + fp16 split (n padded 40->64) ----------------
__global__ void k_w2t(const float* __restrict__ W2) {
    int t = blockIdx.x * blockDim.x + threadIdx.x;
    if (t >= 64 * 256) return;
    int n = t >> 8, k = t & 255;
    float w = (n < NC) ? W2[k * NC + n] : 0.0f;
    __half hi = __float2half_rn(w);
    __half lo = __float2half_rn(w - __half2float(hi));
    g_w2t_hi[t] = hi;
    g_w2t_lo[t] = lo;
}

// ---------------- mma.sync m16n8k16 ----------------
__device__ __forceinline__ void mma16816(float* c, const uint32_t* a, const uint32_t* b) {
    asm volatile(
        "mma.sync.aligned.m16n8k16.row.col.f32.bf16.bf16.f32 "
        "{%0,%1,%2,%3}, {%4,%5,%6,%7}, {%8,%9}, {%0,%1,%2,%3};\n"
        : "+f"(c[0]), "+f"(c[1]), "+f"(c[2]), "+f"(c[3])
        : "r"(a[0]), "r"(a[1]), "r"(a[2]), "r"(a[3]), "r"(b[0]), "r"(b[1]));
}
__device__ __forceinline__ void mma16816h(float* c, const uint32_t* a, const uint32_t* b) {
    asm volatile(
        "mma.sync.aligned.m16n8k16.row.col.f32.f16.f16.f32 "
        "{%0,%1,%2,%3}, {%4,%5,%6,%7}, {%8,%9}, {%0,%1,%2,%3};\n"
        : "+f"(c[0]), "+f"(c[1]), "+f"(c[2]), "+f"(c[3])
        : "r"(a[0]), "r"(a[1]), "r"(a[2]), "r"(a[3]), "r"(b[0]), "r"(b[1]));
}

// ---------------- GEMM1: 128x256 CTA, 512 threads ----------------
#define SA 72
#define SM_AH 0
#define SM_AL (128 * SA * 2)
#define SM_B0 (2 * 128 * SA * 2)
#define BHALF (256 * SA * 2)
#define BSTAGE (2 * BHALF)
#define SM_G1 (SM_B0 + 2 * BSTAGE)          // 184320

__global__ __launch_bounds__(512) void k_gemm1_mma(const float* __restrict__ x,
                                                   const float* __restrict__ bias) {
    extern __shared__ char smem[];
    const uint32_t sbase = smem_u32(smem);
    const int tid = threadIdx.x;
    const int warp = tid >> 5;
    const int lane = tid & 31;
    const int g = lane >> 2;
    const int tg = lane & 3;
    const int wm = (warp >> 3) * 64;
    const int wn = (warp & 7) * 32;
    const int rowBase = blockIdx.x * 128;

    float4 vr[4];
    auto ldgA = [&](int ch) {
        const int k0 = ch * 64;
#pragma unroll
        for (int i = 0; i < 4; i++) {
            int idx = tid + i * 512;
            int r = idx >> 4, c4 = idx & 15;
            int gr = rowBase + r;
            vr[i] = (gr < N_NODES) ? *(const float4*)(x + (size_t)gr * 256 + k0 + c4 * 4)
                                   : make_float4(0.f, 0.f, 0.f, 0.f);
        }
    };
    auto stsA = [&]() {
#pragma unroll
        for (int i = 0; i < 4; i++) {
            int idx = tid + i * 512;
            int r = idx >> 4, c4 = idx & 15;
            float4 v = vr[i];
            __nv_bfloat16 hx = __float2bfloat16(v.x), hy = __float2bfloat16(v.y);
            __nv_bfloat16 hz = __float2bfloat16(v.z), hw = __float2bfloat16(v.w);
            __nv_bfloat16 lx = __float2bfloat16(v.x - __bfloat162float(hx));
            __nv_bfloat16 ly = __float2bfloat16(v.y - __bfloat162float(hy));
            __nv_bfloat16 lz = __float2bfloat16(v.z - __bfloat162float(hz));
            __nv_bfloat16 lw = __float2bfloat16(v.w - __bfloat162float(hw));
            int o = (r * SA + c4 * 4) * 2;
            *(__nv_bfloat162*)(smem + SM_AH + o)     = __halves2bfloat162(hx, hy);
            *(__nv_bfloat162*)(smem + SM_AH + o + 4) = __halves2bfloat162(hz, hw);
            *(__nv_bfloat162*)(smem + SM_AL + o)     = __halves2bfloat162(lx, ly);
            *(__nv_bfloat162*)(smem + SM_AL + o + 4) = __halves2bfloat162(lz, lw);
        }
    };
    auto loadB = [&](int ch, int buf) {
        const int k0 = ch * 64;
        const uint32_t base = sbase + SM_B0 + buf * BSTAGE;
#pragma unroll
        for (int i = 0; i < 4; i++) {
            int idx = tid + i * 512;
            int r = idx >> 3, u = idx & 7;
            uint32_t d = base + (uint32_t)(r * SA + u * 8) * 2;
            CPA16(d, g_w1t_hi + r * 256 + k0 + u * 8);
            CPA16(d + BHALF, g_w1t_lo + r * 256 + k0 + u * 8);
        }
    };

    float acc[4][4][4];
#pragma unroll
    for (int i = 0; i < 4; i++)
#pragma unroll
        for (int j = 0; j < 4; j++)
#pragma unroll
            for (int r = 0; r < 4; r++) acc[i][j][r] = 0.0f;

    ldgA(0);
    loadB(0, 0); CPC();

    for (int ch = 0; ch < 4; ch++) {
        const int buf = ch & 1;
        stsA();
        if (ch < 3) { ldgA(ch + 1); loadB(ch + 1, buf ^ 1); CPC(); CPW(1); }
        else CPW(0);
        __syncthreads();

        const char* Ah = smem + SM_AH;
        const char* Al = smem + SM_AL;
        const char* Bh = smem + SM_B0 + buf * BSTAGE;
        const char* Bl = Bh + BHALF;

#pragma unroll
        for (int ks = 0; ks < 4; ks++) {
            const int kb = ks * 16;
            uint32_t bh[4][2], bl[4][2];
#pragma unroll
            for (int j = 0; j < 4; j++) {
                int n = wn + j * 8 + g;
                int o = (n * SA + kb + tg * 2) * 2;
                bh[j][0] = *(const uint32_t*)(Bh + o);
                bh[j][1] = *(const uint32_t*)(Bh + o + 16);
                bl[j][0] = *(const uint32_t*)(Bl + o);
                bl[j][1] = *(const uint32_t*)(Bl + o + 16);
            }
#pragma unroll
            for (int i = 0; i < 4; i++) {
                int m = wm + i * 16;
                int o0 = ((m + g) * SA + kb + tg * 2) * 2;
                int o1 = ((m + g + 8) * SA + kb + tg * 2) * 2;
                uint32_t ah[4], al[4];
                ah[0] = *(const uint32_t*)(Ah + o0);
                ah[1] = *(const uint32_t*)(Ah + o1);
                ah[2] = *(const uint32_t*)(Ah + o0 + 16);
                ah[3] = *(const uint32_t*)(Ah + o1 + 16);
                al[0] = *(const uint32_t*)(Al + o0);
                al[1] = *(const uint32_t*)(Al + o1);
                al[2] = *(const uint32_t*)(Al + o0 + 16);
                al[3] = *(const uint32_t*)(Al + o1 + 16);
#pragma unroll
                for (int j = 0; j < 4; j++) {
                    mma16816(acc[i][j], ah, bh[j]);
                    mma16816(acc[i][j], ah, bl[j]);
                    mma16816(acc[i][j], al, bh[j]);
                }
            }
        }
        __syncthreads();
    }

    // epilogue: fp16 h1 only
#pragma unroll
    for (int j = 0; j < 4; j++) {
        int col = wn + j * 8 + tg * 2;
        float bx = __ldg(&bias[col]);
        float by = __ldg(&bias[col + 1]);
#pragma unroll
        for (int i = 0; i < 4; i++) {
            int r0 = rowBase + wm + i * 16 + g;
            if (r0 < N_NODES)
                *(__half2*)(g_h1h + (size_t)r0 * 256 + col) =
                    __floats2half2_rn(acc[i][j][0] + bx, acc[i][j][1] + by);
            int r1 = r0 + 8;
            if (r1 < N_NODES)
                *(__half2*)(g_h1h + (size_t)r1 * 256 + col) =
                    __floats2half2_rn(acc[i][j][2] + bx, acc[i][j][3] + by);
        }
    }
}

// ---------------- agg1: 2 warps per node; fp16 gathers, fp32 accum, fp16 out ----------------
__global__ __launch_bounds__(256) void k_agg1() {
    int wid = blockIdx.x * 8 + (threadIdx.x >> 5);
    int node = wid >> 1;
    if (node >= N_NODES) return;
    int half = wid & 1;
    int lane = threadIdx.x & 31;
    int fo = half * 32 + lane;          // uint2 index (4 feats)

    const uint2* hh = (const uint2*)g_h1h;
    float dv = g_dis[node];
    float self = dv * dv;
    uint2 us = __ldg(&hh[(size_t)node * 64 + fo]);
    float2 sa = __half22float2(*(__half2*)&us.x);
    float2 sb = __half22float2(*(__half2*)&us.y);
    float4 acc = make_float4(sa.x * self, sa.y * self, sb.x * self, sb.y * self);

    int p = g_off[node], end = p + g_cnt[node];
    for (; p + 4 <= end; p += 4) {
        int s0 = __ldg(&g_ssrc[p]);
        int s1 = __ldg(&g_ssrc[p + 1]);
        int s2 = __ldg(&g_ssrc[p + 2]);
        int s3 = __ldg(&g_ssrc[p + 3]);
        float n0 = __ldg(&g_snorm[p]);
        float n1 = __ldg(&g_snorm[p + 1]);
        float n2 = __ldg(&g_snorm[p + 2]);
        float n3 = __ldg(&g_snorm[p + 3]);
        uint2 u0 = __ldg(&hh[(size_t)s0 * 64 + fo]);
        uint2 u1 = __ldg(&hh[(size_t)s1 * 64 + fo]);
        uint2 u2 = __ldg(&hh[(size_t)s2 * 64 + fo]);
        uint2 u3 = __ldg(&hh[(size_t)s3 * 64 + fo]);
        float2 a0 = __half22float2(*(__half2*)&u0.x), b0 = __half22float2(*(__half2*)&u0.y);
        float2 a1 = __half22float2(*(__half2*)&u1.x), b1 = __half22float2(*(__half2*)&u1.y);
        float2 a2 = __half22float2(*(__half2*)&u2.x), b2 = __half22float2(*(__half2*)&u2.y);
        float2 a3 = __half22float2(*(__half2*)&u3.x), b3 = __half22float2(*(__half2*)&u3.y);
        acc.x = fmaf(a0.x, n0, acc.x); acc.y = fmaf(a0.y, n0, acc.y);
        acc.z = fmaf(b0.x, n0, acc.z); acc.w = fmaf(b0.y, n0, acc.w);
        acc.x = fmaf(a1.x, n1, acc.x); acc.y = fmaf(a1.y, n1, acc.y);
        acc.z = fmaf(b1.x, n1, acc.z); acc.w = fmaf(b1.y, n1, acc.w);
        acc.x = fmaf(a2.x, n2, acc.x); acc.y = fmaf(a2.y, n2, acc.y);
        acc.z = fmaf(b2.x, n2, acc.z); acc.w = fmaf(b2.y, n2, acc.w);
        acc.x = fmaf(a3.x, n3, acc.x); acc.y = fmaf(a3.y, n3, acc.y);
        acc.z = fmaf(b3.x, n3, acc.z); acc.w = fmaf(b3.y, n3, acc.w);
    }
    for (; p < end; p++) {
        int s = __ldg(&g_ssrc[p]);
        float nm = __ldg(&g_snorm[p]);
        uint2 u = __ldg(&hh[(size_t)s * 64 + fo]);
        float2 a = __half22float2(*(__half2*)&u.x);
        float2 b = __half22float2(*(__half2*)&u.y);
        acc.x = fmaf(a.x, nm, acc.x); acc.y = fmaf(a.y, nm, acc.y);
        acc.z = fmaf(b.x, nm, acc.z); acc.w = fmaf(b.y, nm, acc.w);
    }

    acc.x = fmaxf(acc.x, 0.f); acc.y = fmaxf(acc.y, 0.f);
    acc.z = fmaxf(acc.z, 0.f); acc.w = fmaxf(acc.w, 0.f);
    uint2 outv;
    *(__half2*)&outv.x = __floats2half2_rn(acc.x, acc.y);
    *(__half2*)&outv.y = __floats2half2_rn(acc.z, acc.w);
    ((uint2*)g_a1h)[(size_t)node * 64 + fo] = outv;
}

// ---------------- GEMM2 via mma.sync: h2 = a1h @ W2 + b2 ----------------
// CTA 128 rows x 64 cols(40 padded), 256 threads (8 warps: 4m x 2n), K=256 single stage.
#define G2_SA 264                             // fp16 row stride
#define G2_A 0                                // 128*264*2 = 67584
#define G2_BH 67584                           // 64*264*2 = 33792
#define G2_BL (G2_BH + 33792)                 // 101376
#define SM_G2 (G2_BL + 33792)                 // 135168

__global__ __launch_bounds__(256) void k_gemm2_mma(const float* __restrict__ b2) {
    extern __shared__ char smem[];
    const uint32_t sbase = smem_u32(smem);
    const int tid = threadIdx.x;
    const int warp = tid >> 5;
    const int lane = tid & 31;
    const int g = lane >> 2;
    const int tg = lane & 3;
    const int wm = (warp >> 1) * 32;          // 4 m-groups of 32
    const int wn = (warp & 1) * 32;           // 2 n-groups of 32
    const int rowBase = blockIdx.x * 128;

    // load A: 128 rows x 256 fp16 (a1h padded to N_PAD rows; pad rows zero-init)
#pragma unroll
    for (int i = 0; i < 16; i++) {
        int idx = tid + i * 256;
        int r = idx >> 5, u = idx & 31;       // 32 uint4 per row
        uint32_t d = sbase + G2_A + (uint32_t)(r * G2_SA + u * 8) * 2;
        CPA16(d, g_a1h + (size_t)(rowBase + r) * 256 + u * 8);
    }
    // load B: 64 rows x 256 fp16, hi + lo
#pragma unroll
    for (int i = 0; i < 8; i++) {
        int idx = tid + i * 256;
        int r = idx >> 5, u = idx & 31;
        uint32_t d = sbase + G2_BH + (uint32_t)(r * G2_SA + u * 8) * 2;
        CPA16(d, g_w2t_hi + r * 256 + u * 8);
        CPA16(d + (G2_BL - G2_BH), g_w2t_lo + r * 256 + u * 8);
    }
    CPC(); CPW(0);
    __syncthreads();

    const char* A  = smem + G2_A;
    const char* Bh = smem + G2_BH;
    const char* Bl = smem + G2_BL;

    float acc[2][4][4];
#pragma unroll
    for (int i = 0; i < 2; i++)
#pragma unroll
        for (int j = 0; j < 4; j++)
#pragma unroll
            for (int r = 0; r < 4; r++) acc[i][j][r] = 0.0f;

#pragma unroll
    for (int ks = 0; ks < 16; ks++) {
        const int kb = ks * 16;
        uint32_t bh[4][2], bl[4][2];
#pragma unroll
        for (int j = 0; j < 4; j++) {
            int n = wn + j * 8 + g;
            int o = (n * G2_SA + kb + tg * 2) * 2;
            bh[j][0] = *(const uint32_t*)(Bh + o);
            bh[j][1] = *(const uint32_t*)(Bh + o + 16);
            bl[j][0] = *(const uint32_t*)(Bl + o);
            bl[j][1] = *(const uint32_t*)(Bl + o + 16);
        }
#pragma unroll
        for (int i = 0; i < 2; i++) {
            int m = wm + i * 16;
            int o0 = ((m + g) * G2_SA + kb + tg * 2) * 2;
            int o1 = ((m + g + 8) * G2_SA + kb + tg * 2) * 2;
            uint32_t a[4];
            a[0] = *(const uint32_t*)(A + o0);
            a[1] = *(const uint32_t*)(A + o1);
            a[2] = *(const uint32_t*)(A + o0 + 16);
            a[3] = *(const uint32_t*)(A + o1 + 16);
#pragma unroll
            for (int j = 0; j < 4; j++) {
                mma16816h(acc[i][j], a, bh[j]);
                mma16816h(acc[i][j], a, bl[j]);
            }
        }
    }

    // epilogue: write fp32 h2 + fp16 mirror (cols < 40 only)
#pragma unroll
    for (int j = 0; j < 4; j++) {
        int col = wn + j * 8 + tg * 2;
        if (col >= NC) continue;
        float bx = __ldg(&b2[col]);
        float by = __ldg(&b2[col + 1]);
#pragma unroll
        for (int i = 0; i < 2; i++) {
            int r0 = rowBase + wm + i * 16 + g;
            if (r0 < N_NODES) {
                float vx = acc[i][j][0] + bx, vy = acc[i][j][1] + by;
                *(float2*)(g_h2 + (size_t)r0 * NC + col) = make_float2(vx, vy);
                *(__half2*)(g_h2h + (size_t)r0 * NC + col) = __floats2half2_rn(vx, vy);
            }
            int r1 = r0 + 8;
            if (r1 < N_NODES) {
                float vx = acc[i][j][2] + bx, vy = acc[i][j][3] + by;
                *(float2*)(g_h2 + (size_t)r1 * NC + col) = make_float2(vx, vy);
                *(__half2*)(g_h2h + (size_t)r1 * NC + col) = __floats2half2_rn(vx, vy);
            }
        }
    }
}

// ---------------- agg2 + log_softmax fused (fp16 edge gathers) ----------------
__global__ __launch_bounds__(256) void k_agg2_lsm(float* __restrict__ out) {
    int node = blockIdx.x * 8 + (threadIdx.x >> 5);
    if (node >= N_NODES) return;
    int lane = threadIdx.x & 31;

    float dv = g_dis[node];
    float self = dv * dv;
    const float* hd = g_h2 + (size_t)node * NC;
    float a0 = hd[lane] * self;
    float a1 = (lane < 8) ? hd[lane + 32] * self : 0.f;

    int beg = g_off[node], end = beg + g_cnt[node];
    for (int p = beg; p < end; p++) {
        int s = __ldg(&g_ssrc[p]);
        float nm = __ldg(&g_snorm[p]);
        const __half* hs = g_h2h + (size_t)s * NC;
        a0 = fmaf(__half2float(__ldg(&hs[lane])), nm, a0);
        if (lane < 8) a1 = fmaf(__half2float(__ldg(&hs[lane + 32])), nm, a1);
    }

    float m = (lane < 8) ? fmaxf(a0, a1) : a0;
#pragma unroll
    for (int o = 16; o >= 1; o >>= 1)
        m = fmaxf(m, __shfl_xor_sync(0xFFFFFFFFu, m, o));
    float s = __expf(a0 - m) + ((lane < 8) ? __expf(a1 - m) : 0.f);
#pragma unroll
    for (int o = 16; o >= 1; o >>= 1)
        s += __shfl_xor_sync(0xFFFFFFFFu, s, o);
    float ls = m + logf(s);

    float* op = out + (size_t)node * NC;
    op[lane] = a0 - ls;
    if (lane < 8) op[lane + 32] = a1 - ls;
}

// ---------------- launch (forked: preprocessing || gemm1 path) ----------------
extern "C" void kernel_launch(void* const* d_in, const int* in_sizes, int n_in,
                              void* d_out, int out_size) {
    const float* x  = (const float*)d_in[0];
    const int*   ei = (const int*)d_in[1];
    const float* ew = (const float*)d_in[2];
    const float* W1 = (const float*)d_in[3];
    const float* b1 = (const float*)d_in[4];
    const float* W2 = (const float*)d_in[5];
    const float* b2 = (const float*)d_in[6];
    float* out = (float*)d_out;

    const int* src = ei;
    const int* dst = ei + N_EDGES;

    cudaFuncSetAttribute(k_gemm1_mma, cudaFuncAttributeMaxDynamicSharedMemorySize, SM_G1);
    cudaFuncSetAttribute(k_gemm2_mma, cudaFuncAttributeMaxDynamicSharedMemorySize, SM_G2);

    cudaStream_t s2;
    cudaStreamCreateWithFlags(&s2, cudaStreamNonBlocking);
    cudaEvent_t eF, eJ;
    cudaEventCreateWithFlags(&eF, cudaEventDisableTiming);
    cudaEventCreateWithFlags(&eJ, cudaEventDisableTiming);

    // fork: gemm1 path on s2 (independent of edge preprocessing)
    cudaEventRecord(eF, 0);
    cudaStreamWaitEvent(s2, eF, 0);
    k_w1t<<<256, 256, 0, s2>>>(W1);
    k_w2t<<<64, 256, 0, s2>>>(W2);
    k_gemm1_mma<<<N_PAD / 128, 512, SM_G1, s2>>>(x, b1);
    cudaEventRecord(eJ, s2);

    // preprocessing on main stream
    k_init<<<(N_NODES + 255) / 256, 256>>>();
    k_cnt<<<(N_EDGES + 255) / 256, 256>>>(dst, ew);
    k_fin<<<(N_NODES + 255) / 256, 256>>>();
    k_fill<<<(N_EDGES + 255) / 256, 256>>>(src, dst, ew);

    // join, then dependent chain
    cudaStreamWaitEvent(0, eJ, 0);
    k_agg1<<<(2 * N_NODES + 7) / 8, 256>>>();
    k_gemm2_mma<<<N_PAD / 128, 256, SM_G2>>>(b2);
    k_agg2_lsm<<<(N_NODES + 7) / 8, 256>>>(out);
}